// round 2
// baseline (speedup 1.0000x reference)
#include <cuda_runtime.h>
#include <math.h>

#define B_   8
#define S_   4096
#define E_   512
#define H_   8
#define D_   64
#define M_   (B_ * S_)      // 32768 rows
#define NCH  32             // S-chunks for KV reduction
#define CHS  (S_ / NCH)     // 128 rows per chunk
#define EPS_ 1e-6f

// -------- scratch (device globals; no allocations allowed) --------
__device__ float g_q[(size_t)M_ * E_];
__device__ float g_k[(size_t)M_ * E_];
__device__ float g_v[(size_t)M_ * E_];
__device__ float g_attn[(size_t)M_ * E_];
__device__ float g_kv[B_ * H_ * D_ * D_];            // [bh][d][m]
__device__ float g_ksum[B_ * H_ * D_];               // [bh][d]
__device__ float g_kvp[(size_t)B_ * H_ * NCH * D_ * D_];
__device__ float g_ksp[(size_t)B_ * H_ * NCH * D_];

// ============================================================
// Tiled fp32 GEMM body: C[M,512] = act(A[M,512] @ W[512,512] + b)
// BM=BN=128, BK=16, 256 threads, 8x8 accum per thread.
// ============================================================
__device__ __forceinline__ void gemm_body(const float* __restrict__ A,
                                          const float* __restrict__ W,
                                          const float* __restrict__ bias,
                                          float* __restrict__ C,
                                          bool act)
{
    __shared__ float As[16][132];   // [k][m], padded
    __shared__ float Bs[16][128];   // [k][n]

    const int tid = threadIdx.x;
    const int m0 = blockIdx.x * 128;
    const int n0 = blockIdx.y * 128;
    const int tx = tid & 15;   // n-group
    const int ty = tid >> 4;   // m-group

    float acc[8][8];
#pragma unroll
    for (int i = 0; i < 8; i++)
#pragma unroll
        for (int j = 0; j < 8; j++) acc[i][j] = 0.f;

    const int arow = tid >> 2;          // 0..63
    const int ak   = (tid & 3) * 4;     // 0,4,8,12
    const int bkr  = tid >> 5;          // 0..7
    const int bn   = (tid & 31) * 4;    // 0..124

    for (int k0 = 0; k0 < 512; k0 += 16) {
        // load A tile (128 x 16), transpose into As[k][m]
#pragma unroll
        for (int r = 0; r < 2; r++) {
            int m = arow + r * 64;
            float4 a = *(const float4*)(A + (size_t)(m0 + m) * 512 + k0 + ak);
            As[ak + 0][m] = a.x;
            As[ak + 1][m] = a.y;
            As[ak + 2][m] = a.z;
            As[ak + 3][m] = a.w;
        }
        // load B tile (16 x 128)
#pragma unroll
        for (int r = 0; r < 2; r++) {
            int kr = bkr + r * 8;
            float4 b = *(const float4*)(W + (size_t)(k0 + kr) * 512 + n0 + bn);
            *(float4*)(&Bs[kr][bn]) = b;
        }
        __syncthreads();

#pragma unroll
        for (int kk = 0; kk < 16; kk++) {
            const float4* ap = (const float4*)(&As[kk][ty * 8]);
            const float4* bp = (const float4*)(&Bs[kk][tx * 8]);
            float4 a0 = ap[0], a1 = ap[1];
            float4 b0 = bp[0], b1 = bp[1];
            float af[8] = {a0.x, a0.y, a0.z, a0.w, a1.x, a1.y, a1.z, a1.w};
            float bf[8] = {b0.x, b0.y, b0.z, b0.w, b1.x, b1.y, b1.z, b1.w};
#pragma unroll
            for (int i = 0; i < 8; i++)
#pragma unroll
                for (int j = 0; j < 8; j++)
                    acc[i][j] += af[i] * bf[j];
        }
        __syncthreads();
    }

#pragma unroll
    for (int i = 0; i < 8; i++) {
        int m = m0 + ty * 8 + i;
#pragma unroll
        for (int j = 0; j < 8; j++) {
            int n = n0 + tx * 8 + j;
            float v = acc[i][j] + bias[n];
            if (act) v = (v > 0.f) ? (v + 1.f) : __expf(v);  // elu(x)+1
            C[(size_t)m * 512 + n] = v;
        }
    }
}

// grid (256, 4, 3): z=0 -> Q (act), z=1 -> K (act), z=2 -> V (no act)
__global__ __launch_bounds__(256) void qkv_gemm(const float* __restrict__ x,
                                                const float* __restrict__ Wq, const float* __restrict__ bq,
                                                const float* __restrict__ Wk, const float* __restrict__ bk,
                                                const float* __restrict__ Wv, const float* __restrict__ bv)
{
    const float* W;
    const float* b;
    float* C;
    bool act;
    if (blockIdx.z == 0)      { W = Wq; b = bq; C = g_q; act = true;  }
    else if (blockIdx.z == 1) { W = Wk; b = bk; C = g_k; act = true;  }
    else                      { W = Wv; b = bv; C = g_v; act = false; }
    gemm_body(x, W, b, C, act);
}

// grid (256, 4)
__global__ __launch_bounds__(256) void out_gemm(float* __restrict__ out,
                                                const float* __restrict__ Wo,
                                                const float* __restrict__ bo)
{
    gemm_body(g_attn, Wo, bo, out, false);
}

// ============================================================
// KV state partials: per (bh, chunk) compute kv[d][m] += k[s,d]*v[s,m]
// and ksum[d] over the chunk's 128 rows. grid (NCH, 64), block 256.
// ============================================================
__global__ __launch_bounds__(256) void kv_partial()
{
    const int ch = blockIdx.x;
    const int bh = blockIdx.y;
    const int b  = bh >> 3, h = bh & 7;
    const int tid = threadIdx.x;

    __shared__ float ks[2][64], vs[2][64];

    float acc[16];
#pragma unroll
    for (int j = 0; j < 16; j++) acc[j] = 0.f;
    float ksacc = 0.f;

    const size_t base = ((size_t)(b * S_ + ch * CHS)) * 512 + h * 64;
    const int which = tid >> 7;     // 0/1: s-offset
    const int lane  = tid & 127;

    for (int s = 0; s < CHS; s += 2) {
        size_t roff = base + (size_t)(s + which) * 512;
        if (lane < 64) ks[which][lane]      = g_k[roff + lane];
        else           vs[which][lane - 64] = g_v[roff + lane - 64];
        __syncthreads();
#pragma unroll
        for (int w = 0; w < 2; w++) {
#pragma unroll
            for (int j = 0; j < 16; j++) {
                int d = (tid >> 6) + j * 4;
                int m = tid & 63;
                acc[j] += ks[w][d] * vs[w][m];
            }
        }
        if (tid < 64) ksacc += ks[0][tid] + ks[1][tid];
        __syncthreads();
    }

    const size_t ob = ((size_t)bh * NCH + ch) * 4096;
#pragma unroll
    for (int j = 0; j < 16; j++) g_kvp[ob + tid + j * 256] = acc[j];
    if (tid < 64) g_ksp[((size_t)bh * NCH + ch) * 64 + tid] = ksacc;
}

// Deterministic fixed-order reduction over chunks. grid 64, block 256.
__global__ __launch_bounds__(256) void kv_reduce()
{
    const int bh = blockIdx.x;
    const int tid = threadIdx.x;
    for (int idx = tid; idx < 4096; idx += 256) {
        float s = 0.f;
#pragma unroll
        for (int c = 0; c < NCH; c++)
            s += g_kvp[((size_t)bh * NCH + c) * 4096 + idx];
        g_kv[(size_t)bh * 4096 + idx] = s;
    }
    if (tid < 64) {
        float s = 0.f;
#pragma unroll
        for (int c = 0; c < NCH; c++)
            s += g_ksp[((size_t)bh * NCH + c) * 64 + tid];
        g_ksum[bh * 64 + tid] = s;
    }
}

// ============================================================
// Attention readout: out[l,h,m] = (sum_d q[d]*kv[d][m]) / (q . ksum + eps)
// grid (S/8, B), block 512: 8 rows per block, thread = (h,m).
// ============================================================
__global__ __launch_bounds__(512) void attn_kernel()
{
    const int b  = blockIdx.y;
    const int l0 = blockIdx.x * 8;
    const int tid = threadIdx.x;
    const int h = tid >> 6, m = tid & 63;

    __shared__ float qs[8][512];
    __shared__ float kss[512];

#pragma unroll
    for (int r = 0; r < 8; r++)
        qs[r][tid] = g_q[((size_t)(b * S_ + l0 + r)) * 512 + tid];
    kss[tid] = g_ksum[b * 512 + tid];
    __syncthreads();

    float acc[8], denom[8];
#pragma unroll
    for (int r = 0; r < 8; r++) { acc[r] = 0.f; denom[r] = 0.f; }

    const float* kvp = g_kv + ((size_t)(b * 8 + h)) * 4096 + m;
#pragma unroll 4
    for (int d = 0; d < 64; d++) {
        float kvv = kvp[(size_t)d * 64];
        float ksv = kss[h * 64 + d];
#pragma unroll
        for (int r = 0; r < 8; r++) {
            float qv = qs[r][h * 64 + d];
            acc[r]   += qv * kvv;
            denom[r] += qv * ksv;
        }
    }

#pragma unroll
    for (int r = 0; r < 8; r++) {
        float z = 1.0f / (denom[r] + EPS_);
        g_attn[((size_t)(b * S_ + l0 + r)) * 512 + tid] = acc[r] * z;
    }
}

// ============================================================
extern "C" void kernel_launch(void* const* d_in, const int* in_sizes, int n_in,
                              void* d_out, int out_size)
{
    const float* x  = (const float*)d_in[0];
    const float* Wq = (const float*)d_in[1];
    const float* bq = (const float*)d_in[2];
    const float* Wk = (const float*)d_in[3];
    const float* bk = (const float*)d_in[4];
    const float* Wv = (const float*)d_in[5];
    const float* bv = (const float*)d_in[6];
    const float* Wo = (const float*)d_in[7];
    const float* bo = (const float*)d_in[8];
    float* out = (float*)d_out;

    qkv_gemm<<<dim3(M_ / 128, 512 / 128, 3), 256>>>(x, Wq, bq, Wk, bk, Wv, bv);
    kv_partial<<<dim3(NCH, B_ * H_), 256>>>();
    kv_reduce<<<B_ * H_, 256>>>();
    attn_kernel<<<dim3(S_ / 8, B_), 512>>>();
    out_gemm<<<dim3(M_ / 128, 512 / 128), 256>>>(out, Wo, bo);
}

// round 5
// speedup vs baseline: 2.0413x; 2.0413x over previous
#include <cuda_runtime.h>
#include <cuda_bf16.h>
#include <math.h>
#include <stdint.h>

#define B_   8
#define S_   4096
#define E_   512
#define H_   8
#define D_   64
#define M_   (B_ * S_)      // 32768 rows
#define NCH  32
#define CHS  (S_ / NCH)
#define EPS_ 1e-6f

// -------- scratch (device globals; no allocations allowed) --------
__device__ __align__(16) float g_q[(size_t)M_ * E_];
__device__ __align__(16) float g_k[(size_t)M_ * E_];
__device__ __align__(16) float g_v[(size_t)M_ * E_];
__device__ __align__(16) float g_kv[B_ * H_ * D_ * D_];
__device__ __align__(16) float g_ksum[B_ * H_ * D_];
__device__ __align__(16) float g_kvp[(size_t)B_ * H_ * NCH * D_ * D_];
__device__ __align__(16) float g_ksp[(size_t)B_ * H_ * NCH * D_];
// bf16 split operands
__device__ __align__(16) __nv_bfloat16 g_xh[(size_t)M_ * E_];
__device__ __align__(16) __nv_bfloat16 g_xl[(size_t)M_ * E_];
__device__ __align__(16) __nv_bfloat16 g_ah[(size_t)M_ * E_];
__device__ __align__(16) __nv_bfloat16 g_al[(size_t)M_ * E_];
__device__ __align__(16) __nv_bfloat16 g_wh[4 * 512 * 512];  // transposed [n][k]
__device__ __align__(16) __nv_bfloat16 g_wl[4 * 512 * 512];

// ================= portable PTX helpers (no sm_103a features) =================
static __device__ __forceinline__ uint32_t smem_u32(const void* p) {
    uint32_t a;
    asm("{ .reg .u64 t; cvta.to.shared.u64 t, %1; cvt.u32.u64 %0, t; }" : "=r"(a) : "l"(p));
    return a;
}
static __device__ __forceinline__ void ldsm4(uint32_t* r, uint32_t addr) {
    asm volatile("ldmatrix.sync.aligned.m8n8.x4.shared.b16 {%0,%1,%2,%3}, [%4];"
                 : "=r"(r[0]), "=r"(r[1]), "=r"(r[2]), "=r"(r[3]) : "r"(addr));
}
static __device__ __forceinline__ void mma16816(float* c, const uint32_t* a, const uint32_t* b) {
    asm volatile("mma.sync.aligned.m16n8k16.row.col.f32.bf16.bf16.f32 "
                 "{%0,%1,%2,%3}, {%4,%5,%6,%7}, {%8,%9}, {%0,%1,%2,%3};"
                 : "+f"(c[0]), "+f"(c[1]), "+f"(c[2]), "+f"(c[3])
                 : "r"(a[0]), "r"(a[1]), "r"(a[2]), "r"(a[3]), "r"(b[0]), "r"(b[1]));
}

// ============================================================
// HMMA bf16 3-split GEMM: C[m0:+128, n0:+64] = act(A @ B^T + bias)
// A (hi/lo) [M,512] row-major bf16; B (hi/lo) [N=512,512] K-major bf16 ([n][k]).
// 256 threads = 8 warps (4m x 2n), warp tile 32x32, BK=64.
// SMEM 48KB: Ah(16K) | Al(16K) | Bh(8K) | Bl(8K), XOR-swizzled 16B chunks.
// ============================================================
static __device__ __forceinline__ void gemm_mma_body(
    const __nv_bfloat16* __restrict__ Ah, const __nv_bfloat16* __restrict__ Al,
    const __nv_bfloat16* __restrict__ Bh, const __nv_bfloat16* __restrict__ Bl,
    const float* __restrict__ bias, float* __restrict__ C,
    bool act, int m0, int n0)
{
    __shared__ __align__(1024) uint8_t sm[49152];
    const int tid = threadIdx.x;
    const int wid = tid >> 5, lane = tid & 31;
    const int wm = wid & 3;          // 0..3 -> 32-row group
    const int wn = wid >> 2;         // 0..1 -> 32-col group
    const uint32_t sbase = smem_u32(sm);
    const uint32_t sAh = sbase, sAl = sbase + 16384;
    const uint32_t sBh = sbase + 32768, sBl = sbase + 40960;

    float acc[2][4][4];
#pragma unroll
    for (int i = 0; i < 2; i++)
#pragma unroll
        for (int j = 0; j < 4; j++)
#pragma unroll
            for (int t = 0; t < 4; t++) acc[i][j][t] = 0.f;

    // ldmatrix per-thread row/chunk params
    const int rA  = wm * 32 + (lane & 15);                 // + mt*16
    const int khA = (lane >> 4) & 1;                       // k half (16B)
    const int rB  = wn * 32 + (lane & 7) + ((lane >> 1) & 8);  // + pair*16
    const int khB = (lane >> 3) & 1;
    const int swA = lane & 7;  // rA & 7
    const int swB = lane & 7;  // rB & 7

    const char* Ahb = (const char*)Ah;
    const char* Alb = (const char*)Al;
    const char* Bhb = (const char*)Bh;
    const char* Blb = (const char*)Bl;

    for (int kb = 0; kb < 8; kb++) {
        const int k0 = kb * 64;
        // --- load A tiles: 128 rows x 128B each (hi, lo) ---
#pragma unroll
        for (int i = 0; i < 4; i++) {
            int idx = i * 256 + tid;
            int r = idx >> 3, c = idx & 7;
            uint32_t so = (uint32_t)(r * 128 + ((c ^ (r & 7)) << 4));
            size_t go = ((size_t)(m0 + r) * 512 + k0) * 2 + c * 16;
            *(uint4*)(sm + so)         = *(const uint4*)(Ahb + go);
            *(uint4*)(sm + 16384 + so) = *(const uint4*)(Alb + go);
        }
        // --- load B tiles: 64 rows x 128B each (hi, lo) ---
#pragma unroll
        for (int i = 0; i < 2; i++) {
            int idx = i * 256 + tid;
            int r = idx >> 3, c = idx & 7;
            uint32_t so = (uint32_t)(r * 128 + ((c ^ (r & 7)) << 4));
            size_t go = ((size_t)(n0 + r) * 512 + k0) * 2 + c * 16;
            *(uint4*)(sm + 32768 + so) = *(const uint4*)(Bhb + go);
            *(uint4*)(sm + 40960 + so) = *(const uint4*)(Blb + go);
        }
        __syncthreads();

#pragma unroll
        for (int ks = 0; ks < 4; ks++) {
            uint32_t aH[8], aL[8], bH[8], bL[8];
            int cA = ks * 2 + khA;
            uint32_t aoff = (uint32_t)(rA * 128 + ((cA ^ swA) << 4));
            int cB = ks * 2 + khB;
            uint32_t boff = (uint32_t)(rB * 128 + ((cB ^ swB) << 4));

            ldsm4(aH + 0, sAh + aoff);
            ldsm4(aH + 4, sAh + aoff + 2048);   // mt=1 (+16 rows)
            ldsm4(bH + 0, sBh + boff);
            ldsm4(bH + 4, sBh + boff + 2048);   // n-tiles 2,3 (+16 rows)
#pragma unroll
            for (int mt = 0; mt < 2; mt++)
#pragma unroll
                for (int nt = 0; nt < 4; nt++)
                    mma16816(acc[mt][nt], aH + 4 * mt, bH + nt * 2);

            ldsm4(aL + 0, sAl + aoff);
            ldsm4(aL + 4, sAl + aoff + 2048);
#pragma unroll
            for (int mt = 0; mt < 2; mt++)
#pragma unroll
                for (int nt = 0; nt < 4; nt++)
                    mma16816(acc[mt][nt], aL + 4 * mt, bH + nt * 2);

            ldsm4(bL + 0, sBl + boff);
            ldsm4(bL + 4, sBl + boff + 2048);
#pragma unroll
            for (int mt = 0; mt < 2; mt++)
#pragma unroll
                for (int nt = 0; nt < 4; nt++)
                    mma16816(acc[mt][nt], aH + 4 * mt, bL + nt * 2);
        }
        __syncthreads();
    }

    // --- epilogue ---
    const int g = lane >> 2, t4 = lane & 3;
#pragma unroll
    for (int mt = 0; mt < 2; mt++) {
#pragma unroll
        for (int nt = 0; nt < 4; nt++) {
            int row = m0 + wm * 32 + mt * 16 + g;
            int col = n0 + wn * 32 + nt * 8 + t4 * 2;
            float b0 = bias[col], b1 = bias[col + 1];
            float f0 = acc[mt][nt][0] + b0;
            float f1 = acc[mt][nt][1] + b1;
            float f2 = acc[mt][nt][2] + b0;
            float f3 = acc[mt][nt][3] + b1;
            if (act) {
                f0 = (f0 > 0.f) ? (f0 + 1.f) : __expf(f0);
                f1 = (f1 > 0.f) ? (f1 + 1.f) : __expf(f1);
                f2 = (f2 > 0.f) ? (f2 + 1.f) : __expf(f2);
                f3 = (f3 > 0.f) ? (f3 + 1.f) : __expf(f3);
            }
            *(float2*)(C + (size_t)row * 512 + col)       = make_float2(f0, f1);
            *(float2*)(C + (size_t)(row + 8) * 512 + col) = make_float2(f2, f3);
        }
    }
}

// grid (256, 8, 3): z = matrix (0=Q,1=K,2=V), y = n-tile of 64
__global__ __launch_bounds__(256, 2) void qkv_mma(const float* __restrict__ bq,
                                                  const float* __restrict__ bk,
                                                  const float* __restrict__ bv)
{
    int mat = blockIdx.z;
    const __nv_bfloat16* Bh = g_wh + (size_t)mat * 262144;
    const __nv_bfloat16* Bl = g_wl + (size_t)mat * 262144;
    const float* bias = (mat == 0) ? bq : (mat == 1) ? bk : bv;
    float* C = (mat == 0) ? g_q : (mat == 1) ? g_k : g_v;
    gemm_mma_body(g_xh, g_xl, Bh, Bl, bias, C, mat < 2,
                  blockIdx.x * 128, blockIdx.y * 64);
}

// grid (256, 8)
__global__ __launch_bounds__(256, 2) void out_mma(float* __restrict__ out,
                                                  const float* __restrict__ bo)
{
    gemm_mma_body(g_ah, g_al, g_wh + (size_t)3 * 262144, g_wl + (size_t)3 * 262144,
                  bo, out, false, blockIdx.x * 128, blockIdx.y * 64);
}

// ============================================================
// split x -> bf16 hi/lo
__global__ __launch_bounds__(256) void split_x(const float* __restrict__ x)
{
    size_t i4 = ((size_t)blockIdx.x * 256 + threadIdx.x) * 4;
    float4 v = *(const float4*)(x + i4);
    float vv[4] = {v.x, v.y, v.z, v.w};
    __nv_bfloat16 h[4], l[4];
#pragma unroll
    for (int j = 0; j < 4; j++) {
        h[j] = __float2bfloat16(vv[j]);
        l[j] = __float2bfloat16(vv[j] - __bfloat162float(h[j]));
    }
    *(__nv_bfloat162*)(g_xh + i4)     = __nv_bfloat162(h[0], h[1]);
    *(__nv_bfloat162*)(g_xh + i4 + 2) = __nv_bfloat162(h[2], h[3]);
    *(__nv_bfloat162*)(g_xl + i4)     = __nv_bfloat162(l[0], l[1]);
    *(__nv_bfloat162*)(g_xl + i4 + 2) = __nv_bfloat162(l[2], l[3]);
}

// transpose + split weights: W [k][n] fp32 -> Wt [n][k] bf16 hi/lo. grid(16,16,4) block(32,8)
__global__ __launch_bounds__(256) void tsplit_w(const float* __restrict__ Wq,
                                                const float* __restrict__ Wk,
                                                const float* __restrict__ Wv,
                                                const float* __restrict__ Wo)
{
    const float* W = (blockIdx.z == 0) ? Wq : (blockIdx.z == 1) ? Wk
                   : (blockIdx.z == 2) ? Wv : Wo;
    __nv_bfloat16* oh = g_wh + (size_t)blockIdx.z * 262144;
    __nv_bfloat16* ol = g_wl + (size_t)blockIdx.z * 262144;
    __shared__ float t[32][33];
    int nx = blockIdx.x * 32 + threadIdx.x;
    int k0 = blockIdx.y * 32;
#pragma unroll
    for (int j = 0; j < 4; j++)
        t[threadIdx.y + j * 8][threadIdx.x] = W[(size_t)(k0 + threadIdx.y + j * 8) * 512 + nx];
    __syncthreads();
#pragma unroll
    for (int j = 0; j < 4; j++) {
        int nr = blockIdx.x * 32 + threadIdx.y + j * 8;
        int kc = k0 + threadIdx.x;
        float v = t[threadIdx.x][threadIdx.y + j * 8];
        __nv_bfloat16 h = __float2bfloat16(v);
        oh[(size_t)nr * 512 + kc] = h;
        ol[(size_t)nr * 512 + kc] = __float2bfloat16(v - __bfloat162float(h));
    }
}

// ============================================================
// KV state partials (fp32, deterministic)
__global__ __launch_bounds__(256) void kv_partial()
{
    const int ch = blockIdx.x;
    const int bh = blockIdx.y;
    const int b = bh >> 3, h = bh & 7;
    const int tid = threadIdx.x;

    __shared__ float ks[2][64], vs[2][64];

    float acc[16];
#pragma unroll
    for (int j = 0; j < 16; j++) acc[j] = 0.f;
    float ksacc = 0.f;

    const size_t base = ((size_t)(b * S_ + ch * CHS)) * 512 + h * 64;
    const int which = tid >> 7;
    const int lane = tid & 127;

    for (int s = 0; s < CHS; s += 2) {
        size_t roff = base + (size_t)(s + which) * 512;
        if (lane < 64) ks[which][lane] = g_k[roff + lane];
        else           vs[which][lane - 64] = g_v[roff + lane - 64];
        __syncthreads();
#pragma unroll
        for (int w = 0; w < 2; w++) {
#pragma unroll
            for (int j = 0; j < 16; j++) {
                int d = (tid >> 6) + j * 4;
                int m = tid & 63;
                acc[j] += ks[w][d] * vs[w][m];
            }
        }
        if (tid < 64) ksacc += ks[0][tid] + ks[1][tid];
        __syncthreads();
    }

    const size_t ob = ((size_t)bh * NCH + ch) * 4096;
#pragma unroll
    for (int j = 0; j < 16; j++) g_kvp[ob + tid + j * 256] = acc[j];
    if (tid < 64) g_ksp[((size_t)bh * NCH + ch) * 64 + tid] = ksacc;
}

__global__ __launch_bounds__(256) void kv_reduce()
{
    const int bh = blockIdx.x;
    const int tid = threadIdx.x;
    for (int idx = tid; idx < 4096; idx += 256) {
        float s = 0.f;
#pragma unroll
        for (int c = 0; c < NCH; c++)
            s += g_kvp[((size_t)bh * NCH + c) * 4096 + idx];
        g_kv[(size_t)bh * 4096 + idx] = s;
    }
    if (tid < 64) {
        float s = 0.f;
#pragma unroll
        for (int c = 0; c < NCH; c++)
            s += g_ksp[((size_t)bh * NCH + c) * 64 + tid];
        g_ksum[bh * 64 + tid] = s;
    }
}

// ============================================================
// Attention readout -> writes bf16 hi/lo split directly for the out GEMM
__global__ __launch_bounds__(512) void attn_kernel()
{
    const int b = blockIdx.y;
    const int l0 = blockIdx.x * 8;
    const int tid = threadIdx.x;
    const int h = tid >> 6, m = tid & 63;

    __shared__ float qs[8][512];
    __shared__ float kss[512];

#pragma unroll
    for (int r = 0; r < 8; r++)
        qs[r][tid] = g_q[((size_t)(b * S_ + l0 + r)) * 512 + tid];
    kss[tid] = g_ksum[b * 512 + tid];
    __syncthreads();

    float acc[8], denom[8];
#pragma unroll
    for (int r = 0; r < 8; r++) { acc[r] = 0.f; denom[r] = 0.f; }

    const float* kvp = g_kv + ((size_t)(b * 8 + h)) * 4096 + m;
#pragma unroll 4
    for (int d = 0; d < 64; d++) {
        float kvv = kvp[(size_t)d * 64];
        float ksv = kss[h * 64 + d];
#pragma unroll
        for (int r = 0; r < 8; r++) {
            float qv = qs[r][h * 64 + d];
            acc[r] += qv * kvv;
            denom[r] += qv * ksv;
        }
    }

#pragma unroll
    for (int r = 0; r < 8; r++) {
        float z = 1.0f / (denom[r] + EPS_);
        float v = acc[r] * z;
        size_t idx = ((size_t)(b * S_ + l0 + r)) * 512 + tid;
        __nv_bfloat16 hi = __float2bfloat16(v);
        g_ah[idx] = hi;
        g_al[idx] = __float2bfloat16(v - __bfloat162float(hi));
    }
}

// ============================================================
extern "C" void kernel_launch(void* const* d_in, const int* in_sizes, int n_in,
                              void* d_out, int out_size)
{
    const float* x  = (const float*)d_in[0];
    const float* Wq = (const float*)d_in[1];
    const float* bq = (const float*)d_in[2];
    const float* Wk = (const float*)d_in[3];
    const float* bk = (const float*)d_in[4];
    const float* Wv = (const float*)d_in[5];
    const float* bv = (const float*)d_in[6];
    const float* Wo = (const float*)d_in[7];
    const float* bo = (const float*)d_in[8];
    float* out = (float*)d_out;

    split_x<<<(M_ * E_) / (256 * 4), 256>>>(x);
    tsplit_w<<<dim3(16, 16, 4), dim3(32, 8)>>>(Wq, Wk, Wv, Wo);
    qkv_mma<<<dim3(M_ / 128, 8, 3), 256>>>(bq, bk, bv);
    kv_partial<<<dim3(NCH, B_ * H_), 256>>>();
    kv_reduce<<<B_ * H_, 256>>>();
    attn_kernel<<<dim3(S_ / 8, B_), 512>>>();
    out_mma<<<dim3(M_ / 128, 8), 256>>>(out, bo);
}